// round 5
// baseline (speedup 1.0000x reference)
#include <cuda_runtime.h>
#include <cstdint>

// ---------------------------------------------------------------------------
// Generic-path inverse table (only used by the fallback kernel).
// ---------------------------------------------------------------------------
#define INV_CAP 8192
__device__ int g_inv[INV_CAP];

__global__ void build_inv_kernel(const int* __restrict__ idx, int K, int F) {
    int i = blockIdx.x * blockDim.x + threadIdx.x;
    if (i < F) g_inv[i] = -1;
    __syncthreads();
    if (i < K) {
        int f = idx[i];
        if (f >= 0 && f < INV_CAP) g_inv[f] = i;
    }
}

// ---------------------------------------------------------------------------
// Fast path: F == 256, K == 128. TWO rows per warp, float4/int4 vectorized,
// 6 front-batched 16B loads per thread (MLP_p1=6), inverse table built
// per-block in smem, 32-bit addressing, streaming cache hints.
// ---------------------------------------------------------------------------
__global__ __launch_bounds__(256) void dropout_fast2_kernel(
    const float4* __restrict__ X4,   // rows * 64 float4
    const int4*  __restrict__ M4,    // rows * 32 int4
    const int*   __restrict__ idx,   // [128]
    float4*      __restrict__ O4,
    unsigned rows, float inv_K)
{
    __shared__ int s_inv[256];
    __shared__ int s_mask[16][128];  // 8 warps x 2 rows

    const int tid  = threadIdx.x;
    const int warp = tid >> 5;
    const int lane = tid & 31;

    const unsigned row0 = blockIdx.x * 16u + (unsigned)warp * 2u;
    const unsigned row1 = row0 + 1u;
    const bool v0 = row0 < rows;
    const bool v1 = row1 < rows;

    const unsigned xb0 = v0 ? row0 * 64u : 0u;
    const unsigned xb1 = v1 ? row1 * 64u : 0u;
    const unsigned mb0 = v0 ? row0 * 32u : 0u;
    const unsigned mb1 = v1 ? row1 * 32u : 0u;

    // Front-batched wide loads: 6 independent 16B LDGs in flight per thread.
    const float4 a0 = __ldcs(&X4[xb0 + lane]);
    const float4 b0 = __ldcs(&X4[xb0 + 32 + lane]);
    const float4 a1 = __ldcs(&X4[xb1 + lane]);
    const float4 b1 = __ldcs(&X4[xb1 + 32 + lane]);
    const int4   m0 = __ldcs(&M4[mb0 + lane]);
    const int4   m1 = __ldcs(&M4[mb1 + lane]);
    const int idx_f = (tid < 128) ? idx[tid] : -1;

    // Build inverse table in smem (latency of the global loads overlaps this).
    s_inv[tid] = -1;
    __syncthreads();
    if (idx_f >= 0 && idx_f < 256) s_inv[idx_f] = tid;
    *reinterpret_cast<int4*>(&s_mask[warp * 2 + 0][lane * 4]) = m0;
    *reinterpret_cast<int4*>(&s_mask[warp * 2 + 1][lane * 4]) = m1;
    __syncthreads();

    const int fa = lane * 4;        // channels of the 'a' float4
    const int fb = 128 + lane * 4;  // channels of the 'b' float4

    int ka[4], kb[4];
    #pragma unroll
    for (int j = 0; j < 4; j++) {
        ka[j] = s_inv[fa + j];
        kb[j] = s_inv[fb + j];
    }

    const float xa0[4] = {a0.x, a0.y, a0.z, a0.w};
    const float xb0v[4] = {b0.x, b0.y, b0.z, b0.w};
    const float xa1[4] = {a1.x, a1.y, a1.z, a1.w};
    const float xb1v[4] = {b1.x, b1.y, b1.z, b1.w};

    int ma0[4], mbv0[4], ma1[4], mbv1[4];
    float d0 = 0.0f, d1 = 0.0f;
    #pragma unroll
    for (int j = 0; j < 4; j++) {
        ma0[j]  = (ka[j] >= 0) ? s_mask[warp * 2 + 0][ka[j]] : 0;
        mbv0[j] = (kb[j] >= 0) ? s_mask[warp * 2 + 0][kb[j]] : 0;
        ma1[j]  = (ka[j] >= 0) ? s_mask[warp * 2 + 1][ka[j]] : 0;
        mbv1[j] = (kb[j] >= 0) ? s_mask[warp * 2 + 1][kb[j]] : 0;
        if (ma0[j])  d0 += xa0[j];
        if (mbv0[j]) d0 += xb0v[j];
        if (ma1[j])  d1 += xa1[j];
        if (mbv1[j]) d1 += xb1v[j];
    }

    #pragma unroll
    for (int off = 16; off > 0; off >>= 1) {
        d0 += __shfl_xor_sync(0xFFFFFFFFu, d0, off);
        d1 += __shfl_xor_sync(0xFFFFFFFFu, d1, off);
    }
    const float comp0 = d0 * inv_K;
    const float comp1 = d1 * inv_K;

    float oa0[4], ob0[4], oa1[4], ob1[4];
    #pragma unroll
    for (int j = 0; j < 4; j++) {
        oa0[j] = (ka[j] >= 0) ? ((ma0[j]  ? 0.0f : xa0[j])  + comp0) : xa0[j];
        ob0[j] = (kb[j] >= 0) ? ((mbv0[j] ? 0.0f : xb0v[j]) + comp0) : xb0v[j];
        oa1[j] = (ka[j] >= 0) ? ((ma1[j]  ? 0.0f : xa1[j])  + comp1) : xa1[j];
        ob1[j] = (kb[j] >= 0) ? ((mbv1[j] ? 0.0f : xb1v[j]) + comp1) : xb1v[j];
    }

    if (v0) {
        __stcs(&O4[xb0 + lane],      make_float4(oa0[0], oa0[1], oa0[2], oa0[3]));
        __stcs(&O4[xb0 + 32 + lane], make_float4(ob0[0], ob0[1], ob0[2], ob0[3]));
    }
    if (v1) {
        __stcs(&O4[xb1 + lane],      make_float4(oa1[0], oa1[1], oa1[2], oa1[3]));
        __stcs(&O4[xb1 + 32 + lane], make_float4(ob1[0], ob1[1], ob1[2], ob1[3]));
    }
}

// ---------------------------------------------------------------------------
// Generic fallback: one block per row (uses g_inv built by prologue).
// ---------------------------------------------------------------------------
__global__ __launch_bounds__(1024) void dropout_generic_kernel(
    const float* __restrict__ X,
    const int* __restrict__ mask,
    float* __restrict__ out,
    int K, int F, float inv_K)
{
    __shared__ float warp_sums[32];
    __shared__ float s_comp;

    const int row = blockIdx.x;
    const int f   = threadIdx.x;
    const size_t base = (size_t)row * (size_t)F;

    float x = 0.0f;
    int k = -1, m = 0;
    if (f < F) {
        x = X[base + f];
        k = g_inv[f];
        if (k >= 0) m = mask[(size_t)row * (size_t)K + (size_t)k];
    }

    float d = (k >= 0 && m != 0) ? x : 0.0f;
    #pragma unroll
    for (int off = 16; off > 0; off >>= 1)
        d += __shfl_xor_sync(0xFFFFFFFFu, d, off);

    const int lane = threadIdx.x & 31;
    const int wid  = threadIdx.x >> 5;
    if (lane == 0) warp_sums[wid] = d;
    __syncthreads();

    if (wid == 0) {
        int nwarps = (blockDim.x + 31) >> 5;
        float s = (lane < nwarps) ? warp_sums[lane] : 0.0f;
        #pragma unroll
        for (int off = 16; off > 0; off >>= 1)
            s += __shfl_xor_sync(0xFFFFFFFFu, s, off);
        if (lane == 0) s_comp = s * inv_K;
    }
    __syncthreads();

    if (f < F) {
        float comp = s_comp;
        out[base + f] = (k >= 0) ? ((m != 0 ? 0.0f : x) + comp) : x;
    }
}

extern "C" void kernel_launch(void* const* d_in, const int* in_sizes, int n_in,
                              void* d_out, int out_size)
{
    const float* X    = (const float*)d_in[0];
    const int*   idx  = (const int*)d_in[1];
    const int*   mask = (const int*)d_in[2];
    float*       out  = (float*)d_out;

    const int  K    = in_sizes[1];                     // 128
    const long rows = (long)in_sizes[2] / K;           // B*C*T = 262144
    const int  F    = (int)((long)in_sizes[0] / rows); // 256

    if (F == 256 && K == 128 && rows < (1L << 24)) {
        const unsigned nblocks = (unsigned)((rows + 15) / 16);
        dropout_fast2_kernel<<<nblocks, 256>>>(
            (const float4*)X, (const int4*)mask, idx, (float4*)out,
            (unsigned)rows, 1.0f / (float)K);
    } else {
        build_inv_kernel<<<(F > K ? (F + 255) / 256 : (K + 255) / 256), 256>>>(idx, K, F);
        int threads = ((F + 31) / 32) * 32;
        if (threads > 1024) threads = 1024;
        dropout_generic_kernel<<<(unsigned)rows, threads>>>(X, mask, out, K, F, 1.0f / (float)K);
    }
}

// round 6
// speedup vs baseline: 1.0088x; 1.0088x over previous
#include <cuda_runtime.h>
#include <cstdint>

// ---------------------------------------------------------------------------
// Generic-path inverse table (only used by the fallback kernel).
// ---------------------------------------------------------------------------
#define INV_CAP 8192
__device__ int g_inv[INV_CAP];

__global__ void build_inv_kernel(const int* __restrict__ idx, int K, int F) {
    int i = blockIdx.x * blockDim.x + threadIdx.x;
    if (i < F) g_inv[i] = -1;
    __syncthreads();
    if (i < K) {
        int f = idx[i];
        if (f >= 0 && f < INV_CAP) g_inv[f] = i;
    }
}

// ---------------------------------------------------------------------------
// Fast path: F == 256, K == 128. TWO rows per warp, float4/int4 vectorized,
// 6 front-batched 16B loads per thread (MLP_p1=6), inverse table built
// per-block in smem, 32-bit addressing, streaming cache hints.
// ---------------------------------------------------------------------------
__global__ __launch_bounds__(256) void dropout_fast2_kernel(
    const float4* __restrict__ X4,   // rows * 64 float4
    const int4*  __restrict__ M4,    // rows * 32 int4
    const int*   __restrict__ idx,   // [128]
    float4*      __restrict__ O4,
    unsigned rows, float inv_K)
{
    __shared__ int s_inv[256];
    __shared__ int s_mask[16][128];  // 8 warps x 2 rows

    const int tid  = threadIdx.x;
    const int warp = tid >> 5;
    const int lane = tid & 31;

    const unsigned row0 = blockIdx.x * 16u + (unsigned)warp * 2u;
    const unsigned row1 = row0 + 1u;
    const bool v0 = row0 < rows;
    const bool v1 = row1 < rows;

    const unsigned xb0 = v0 ? row0 * 64u : 0u;
    const unsigned xb1 = v1 ? row1 * 64u : 0u;
    const unsigned mb0 = v0 ? row0 * 32u : 0u;
    const unsigned mb1 = v1 ? row1 * 32u : 0u;

    // Front-batched wide loads: 6 independent 16B LDGs in flight per thread.
    const float4 a0 = __ldcs(&X4[xb0 + lane]);
    const float4 b0 = __ldcs(&X4[xb0 + 32 + lane]);
    const float4 a1 = __ldcs(&X4[xb1 + lane]);
    const float4 b1 = __ldcs(&X4[xb1 + 32 + lane]);
    const int4   m0 = __ldcs(&M4[mb0 + lane]);
    const int4   m1 = __ldcs(&M4[mb1 + lane]);
    const int idx_f = (tid < 128) ? idx[tid] : -1;

    // Build inverse table in smem (latency of the global loads overlaps this).
    s_inv[tid] = -1;
    __syncthreads();
    if (idx_f >= 0 && idx_f < 256) s_inv[idx_f] = tid;
    *reinterpret_cast<int4*>(&s_mask[warp * 2 + 0][lane * 4]) = m0;
    *reinterpret_cast<int4*>(&s_mask[warp * 2 + 1][lane * 4]) = m1;
    __syncthreads();

    const int fa = lane * 4;        // channels of the 'a' float4
    const int fb = 128 + lane * 4;  // channels of the 'b' float4

    int ka[4], kb[4];
    #pragma unroll
    for (int j = 0; j < 4; j++) {
        ka[j] = s_inv[fa + j];
        kb[j] = s_inv[fb + j];
    }

    const float xa0[4] = {a0.x, a0.y, a0.z, a0.w};
    const float xb0v[4] = {b0.x, b0.y, b0.z, b0.w};
    const float xa1[4] = {a1.x, a1.y, a1.z, a1.w};
    const float xb1v[4] = {b1.x, b1.y, b1.z, b1.w};

    int ma0[4], mbv0[4], ma1[4], mbv1[4];
    float d0 = 0.0f, d1 = 0.0f;
    #pragma unroll
    for (int j = 0; j < 4; j++) {
        ma0[j]  = (ka[j] >= 0) ? s_mask[warp * 2 + 0][ka[j]] : 0;
        mbv0[j] = (kb[j] >= 0) ? s_mask[warp * 2 + 0][kb[j]] : 0;
        ma1[j]  = (ka[j] >= 0) ? s_mask[warp * 2 + 1][ka[j]] : 0;
        mbv1[j] = (kb[j] >= 0) ? s_mask[warp * 2 + 1][kb[j]] : 0;
        if (ma0[j])  d0 += xa0[j];
        if (mbv0[j]) d0 += xb0v[j];
        if (ma1[j])  d1 += xa1[j];
        if (mbv1[j]) d1 += xb1v[j];
    }

    #pragma unroll
    for (int off = 16; off > 0; off >>= 1) {
        d0 += __shfl_xor_sync(0xFFFFFFFFu, d0, off);
        d1 += __shfl_xor_sync(0xFFFFFFFFu, d1, off);
    }
    const float comp0 = d0 * inv_K;
    const float comp1 = d1 * inv_K;

    float oa0[4], ob0[4], oa1[4], ob1[4];
    #pragma unroll
    for (int j = 0; j < 4; j++) {
        oa0[j] = (ka[j] >= 0) ? ((ma0[j]  ? 0.0f : xa0[j])  + comp0) : xa0[j];
        ob0[j] = (kb[j] >= 0) ? ((mbv0[j] ? 0.0f : xb0v[j]) + comp0) : xb0v[j];
        oa1[j] = (ka[j] >= 0) ? ((ma1[j]  ? 0.0f : xa1[j])  + comp1) : xa1[j];
        ob1[j] = (kb[j] >= 0) ? ((mbv1[j] ? 0.0f : xb1v[j]) + comp1) : xb1v[j];
    }

    if (v0) {
        __stcs(&O4[xb0 + lane],      make_float4(oa0[0], oa0[1], oa0[2], oa0[3]));
        __stcs(&O4[xb0 + 32 + lane], make_float4(ob0[0], ob0[1], ob0[2], ob0[3]));
    }
    if (v1) {
        __stcs(&O4[xb1 + lane],      make_float4(oa1[0], oa1[1], oa1[2], oa1[3]));
        __stcs(&O4[xb1 + 32 + lane], make_float4(ob1[0], ob1[1], ob1[2], ob1[3]));
    }
}

// ---------------------------------------------------------------------------
// Generic fallback: one block per row (uses g_inv built by prologue).
// ---------------------------------------------------------------------------
__global__ __launch_bounds__(1024) void dropout_generic_kernel(
    const float* __restrict__ X,
    const int* __restrict__ mask,
    float* __restrict__ out,
    int K, int F, float inv_K)
{
    __shared__ float warp_sums[32];
    __shared__ float s_comp;

    const int row = blockIdx.x;
    const int f   = threadIdx.x;
    const size_t base = (size_t)row * (size_t)F;

    float x = 0.0f;
    int k = -1, m = 0;
    if (f < F) {
        x = X[base + f];
        k = g_inv[f];
        if (k >= 0) m = mask[(size_t)row * (size_t)K + (size_t)k];
    }

    float d = (k >= 0 && m != 0) ? x : 0.0f;
    #pragma unroll
    for (int off = 16; off > 0; off >>= 1)
        d += __shfl_xor_sync(0xFFFFFFFFu, d, off);

    const int lane = threadIdx.x & 31;
    const int wid  = threadIdx.x >> 5;
    if (lane == 0) warp_sums[wid] = d;
    __syncthreads();

    if (wid == 0) {
        int nwarps = (blockDim.x + 31) >> 5;
        float s = (lane < nwarps) ? warp_sums[lane] : 0.0f;
        #pragma unroll
        for (int off = 16; off > 0; off >>= 1)
            s += __shfl_xor_sync(0xFFFFFFFFu, s, off);
        if (lane == 0) s_comp = s * inv_K;
    }
    __syncthreads();

    if (f < F) {
        float comp = s_comp;
        out[base + f] = (k >= 0) ? ((m != 0 ? 0.0f : x) + comp) : x;
    }
}

extern "C" void kernel_launch(void* const* d_in, const int* in_sizes, int n_in,
                              void* d_out, int out_size)
{
    const float* X    = (const float*)d_in[0];
    const int*   idx  = (const int*)d_in[1];
    const int*   mask = (const int*)d_in[2];
    float*       out  = (float*)d_out;

    const int  K    = in_sizes[1];                     // 128
    const long rows = (long)in_sizes[2] / K;           // B*C*T = 262144
    const int  F    = (int)((long)in_sizes[0] / rows); // 256

    if (F == 256 && K == 128 && rows < (1L << 24)) {
        const unsigned nblocks = (unsigned)((rows + 15) / 16);
        dropout_fast2_kernel<<<nblocks, 256>>>(
            (const float4*)X, (const int4*)mask, idx, (float4*)out,
            (unsigned)rows, 1.0f / (float)K);
    } else {
        build_inv_kernel<<<(F > K ? (F + 255) / 256 : (K + 255) / 256), 256>>>(idx, K, F);
        int threads = ((F + 31) / 32) * 32;
        if (threads > 1024) threads = 1024;
        dropout_generic_kernel<<<(unsigned)rows, threads>>>(X, mask, out, K, F, 1.0f / (float)K);
    }
}